// round 1
// baseline (speedup 1.0000x reference)
#include <cuda_runtime.h>
#include <math.h>

#define B_   8
#define T_   30000
#define L_   6
#define H_   128
#define W_   128
#define D_   32
#define HID_ 256

// Folded shortcut: blk0_ws @ fc_p_w  (32x3) and blk0_ws @ fc_p_b (32)
__device__ float g_foldW[32 * 3];
__device__ float g_foldB[32];

__global__ void fold_kernel(const float* __restrict__ ws,
                            const float* __restrict__ fw,
                            const float* __restrict__ fb) {
    int o = threadIdx.x;
    if (o >= 32) return;
    float a0 = 0.f, a1 = 0.f, a2 = 0.f, ab = 0.f;
    for (int k = 0; k < HID_; k++) {
        float w = ws[o * HID_ + k];
        a0 = fmaf(w, fw[k * 3 + 0], a0);
        a1 = fmaf(w, fw[k * 3 + 1], a1);
        a2 = fmaf(w, fw[k * 3 + 2], a2);
        ab = fmaf(w, fb[k], ab);
    }
    g_foldW[o * 3 + 0] = a0;
    g_foldW[o * 3 + 1] = a1;
    g_foldW[o * 3 + 2] = a2;
    g_foldB[o] = ab;
}

// ---- shared memory layout (float offsets) ----
#define OW0   0        /* blk0_w0      [32][256]  8192 */
#define OW1   8192     /* blk0_w1      [32][32]   1024 */
#define OBW0  9216     /* blk_w0    [4][32][32]   4096 */
#define OBW1  13312    /* blk_w1    [4][32][32]   4096 */
#define OFPW  17408    /* fc_p_w^T     [3][256]    768 */
#define OFPB  18176    /* fc_p_b          [256]    256 */
#define OB0   18432    /* blk0_b0          [32]     32 */
#define OB1   18464    /* blk0_b1          [32]     32 */
#define OBB0  18496    /* blk_b0        [4][32]    128 */
#define OBB1  18624    /* blk_b1        [4][32]    128 */
#define OFW   18752    /* foldW        [32][3]      96 */
#define OFB   18848    /* foldB           [32]      32 */
#define OOUTW 18880    /* fc_out_w        [32]      32 */
#define OA    18912    /* A          [6][2][3]      36 */
#define OOUTB 18948    /* fc_out_b                   1 */
#define SMEM_FLOATS 18949
#define SMEM_BYTES  (SMEM_FLOATS * 4)

__global__ __launch_bounds__(256, 2)
void decoder_kernel(const float* __restrict__ p,
                    const float* __restrict__ c,
                    const float* __restrict__ C_mat,
                    const float* __restrict__ blk0_w0,
                    const float* __restrict__ blk0_b0,
                    const float* __restrict__ blk0_w1,
                    const float* __restrict__ blk0_b1,
                    const float* __restrict__ blk_w0,
                    const float* __restrict__ blk_b0,
                    const float* __restrict__ blk_w1,
                    const float* __restrict__ blk_b1,
                    const float* __restrict__ fc_out_w,
                    const float* __restrict__ fc_out_b,
                    const float* __restrict__ fc_p_w,
                    const float* __restrict__ fc_p_b,
                    float* __restrict__ out) {
    extern __shared__ float s[];
    const int tid = threadIdx.x;
    const int b   = blockIdx.y;

    // ---- cooperative weight staging ----
    for (int i = tid; i < 8192; i += 256) s[OW0 + i]  = blk0_w0[i];
    for (int i = tid; i < 1024; i += 256) s[OW1 + i]  = blk0_w1[i];
    for (int i = tid; i < 4096; i += 256) s[OBW0 + i] = blk_w0[i];
    for (int i = tid; i < 4096; i += 256) s[OBW1 + i] = blk_w1[i];
    for (int i = tid; i < 768; i += 256) {                 // transpose fc_p_w -> [3][256]
        int j = i / 256, k = i % 256;
        s[OFPW + i] = fc_p_w[k * 3 + j];
    }
    for (int i = tid; i < 256; i += 256) s[OFPB + i] = fc_p_b[i];
    if (tid < 32)  s[OB0 + tid]  = blk0_b0[tid];
    if (tid < 32)  s[OB1 + tid]  = blk0_b1[tid];
    if (tid < 128) s[OBB0 + tid] = blk_b0[tid];
    if (tid < 128) s[OBB1 + tid] = blk_b1[tid];
    if (tid < 96)  s[OFW + tid]  = g_foldW[tid];
    if (tid < 32)  s[OFB + tid]  = g_foldB[tid];
    if (tid < 32)  s[OOUTW + tid] = fc_out_w[tid];
    if (tid == 0)  s[OOUTB] = fc_out_b[0];
    if (tid < 36) {
        int l = tid / 6, r = tid % 6, i2 = r / 3, j = r % 3;
        float denom = C_mat[((b * L_ + l) * 4 + 3) * 3 + 0] + 0.05f;
        s[OA + tid] = C_mat[((b * L_ + l) * 4 + i2) * 3 + j] * (63.5f / (0.55f * denom));
    }
    __syncthreads();

    const int t = blockIdx.x * 256 + tid;
    if (t >= T_) return;

    const float* pp = p + ((size_t)b * T_ + t) * 3;
    const float p0 = pp[0], p1 = pp[1], p2 = pp[2];

    // ---- bilinear gather + view-sum -> feat[32] ----
    float feat[32];
#pragma unroll
    for (int d = 0; d < 32; d++) feat[d] = 0.f;

#pragma unroll 1
    for (int l = 0; l < L_; l++) {
        const float* Al = s + OA + l * 6;
        float x = fmaf(Al[0], p0, fmaf(Al[1], p1, fmaf(Al[2], p2, 63.5f)));
        float y = fmaf(Al[3], p0, fmaf(Al[4], p1, fmaf(Al[5], p2, 63.5f)));
        float x0f = floorf(x), x1f = ceilf(x);
        float y0f = floorf(y), y1f = ceilf(y);
        float dx = x1f - x, dy = y1f - y;
        int ix0 = min(max((int)x0f, 0), H_ - 1);
        int ix1 = min(max((int)x1f, 0), H_ - 1);
        int iy0 = min(max((int)y0f, 0), W_ - 1);
        int iy1 = min(max((int)y1f, 0), W_ - 1);
        const float* cb = c + ((size_t)(b * L_ + l)) * (H_ * W_ * D_);
        const float4* f11 = (const float4*)(cb + (ix0 * W_ + iy0) * D_);
        const float4* f12 = (const float4*)(cb + (ix1 * W_ + iy0) * D_);
        const float4* f21 = (const float4*)(cb + (ix0 * W_ + iy1) * D_);
        const float4* f22 = (const float4*)(cb + (ix1 * W_ + iy1) * D_);
        float w11 = dx * dy;
        float w12 = (1.f - dx) * dy;
        float w21 = dx * (1.f - dy);
        float w22 = (1.f - dx) * (1.f - dy);
#pragma unroll
        for (int d = 0; d < 8; d++) {
            float4 a = f11[d], bb = f12[d], cc = f21[d], dd = f22[d];
            feat[4 * d + 0] = fmaf(w11, a.x, fmaf(w12, bb.x, fmaf(w21, cc.x, fmaf(w22, dd.x, feat[4 * d + 0]))));
            feat[4 * d + 1] = fmaf(w11, a.y, fmaf(w12, bb.y, fmaf(w21, cc.y, fmaf(w22, dd.y, feat[4 * d + 1]))));
            feat[4 * d + 2] = fmaf(w11, a.z, fmaf(w12, bb.z, fmaf(w21, cc.z, fmaf(w22, dd.z, feat[4 * d + 2]))));
            feat[4 * d + 3] = fmaf(w11, a.w, fmaf(w12, bb.w, fmaf(w21, cc.w, fmaf(w22, dd.w, feat[4 * d + 3]))));
        }
    }

    // ---- 3 -> 256 (relu) -> 32 fused, accumulating h ----
    float acc[32];
#pragma unroll
    for (int o = 0; o < 32; o++) acc[o] = s[OB0 + o];

#pragma unroll 1
    for (int k = 0; k < HID_; k += 4) {
        float4 wa = *(const float4*)&s[OFPW + k];
        float4 wb = *(const float4*)&s[OFPW + 256 + k];
        float4 wc = *(const float4*)&s[OFPW + 512 + k];
        float4 bv = *(const float4*)&s[OFPB + k];
        float r0 = fmaxf(fmaf(wa.x, p0, fmaf(wb.x, p1, fmaf(wc.x, p2, bv.x))), 0.f);
        float r1 = fmaxf(fmaf(wa.y, p0, fmaf(wb.y, p1, fmaf(wc.y, p2, bv.y))), 0.f);
        float r2 = fmaxf(fmaf(wa.z, p0, fmaf(wb.z, p1, fmaf(wc.z, p2, bv.z))), 0.f);
        float r3 = fmaxf(fmaf(wa.w, p0, fmaf(wb.w, p1, fmaf(wc.w, p2, bv.w))), 0.f);
#pragma unroll
        for (int o = 0; o < 32; o++) {
            float4 w = *(const float4*)&s[OW0 + o * HID_ + k];
            acc[o] = fmaf(w.x, r0, fmaf(w.y, r1, fmaf(w.z, r2, fmaf(w.w, r3, acc[o]))));
        }
    }

    // relu(h) in place
#pragma unroll
    for (int o = 0; o < 32; o++) acc[o] = fmaxf(acc[o], 0.f);

    // net = foldW*p + foldB + blk0_b1 + feat, then += blk0_w1 @ relu(h)
    float net[32];
#pragma unroll
    for (int o = 0; o < 32; o++) {
        net[o] = fmaf(s[OFW + o * 3 + 0], p0,
                 fmaf(s[OFW + o * 3 + 1], p1,
                 fmaf(s[OFW + o * 3 + 2], p2,
                      s[OFB + o] + s[OB1 + o] + feat[o])));
    }
#pragma unroll
    for (int k = 0; k < 32; k += 4) {
        float r0 = acc[k], r1 = acc[k + 1], r2 = acc[k + 2], r3 = acc[k + 3];
#pragma unroll
        for (int o = 0; o < 32; o++) {
            float4 w = *(const float4*)&s[OW1 + o * 32 + k];
            net[o] = fmaf(w.x, r0, fmaf(w.y, r1, fmaf(w.z, r2, fmaf(w.w, r3, net[o]))));
        }
    }

    // ---- 4 residual blocks (32 -> 32 -> 32) ----
#pragma unroll 1
    for (int i = 0; i < 4; i++) {
        const float* w0p = s + OBW0 + i * 1024;
        const float* w1p = s + OBW1 + i * 1024;
        const float* b0p = s + OBB0 + i * 32;
        const float* b1p = s + OBB1 + i * 32;
        float h[32];
#pragma unroll
        for (int o = 0; o < 32; o++) h[o] = b0p[o];
#pragma unroll
        for (int k = 0; k < 32; k += 4) {
            float r0 = fmaxf(net[k], 0.f);
            float r1 = fmaxf(net[k + 1], 0.f);
            float r2 = fmaxf(net[k + 2], 0.f);
            float r3 = fmaxf(net[k + 3], 0.f);
#pragma unroll
            for (int o = 0; o < 32; o++) {
                float4 w = *(const float4*)&w0p[o * 32 + k];
                h[o] = fmaf(w.x, r0, fmaf(w.y, r1, fmaf(w.z, r2, fmaf(w.w, r3, h[o]))));
            }
        }
#pragma unroll
        for (int o = 0; o < 32; o++) net[o] += b1p[o] + feat[o];
#pragma unroll
        for (int k = 0; k < 32; k += 4) {
            float r0 = fmaxf(h[k], 0.f);
            float r1 = fmaxf(h[k + 1], 0.f);
            float r2 = fmaxf(h[k + 2], 0.f);
            float r3 = fmaxf(h[k + 3], 0.f);
#pragma unroll
            for (int o = 0; o < 32; o++) {
                float4 w = *(const float4*)&w1p[o * 32 + k];
                net[o] = fmaf(w.x, r0, fmaf(w.y, r1, fmaf(w.z, r2, fmaf(w.w, r3, net[o]))));
            }
        }
    }

    // ---- output head ----
    float o_ = s[OOUTB];
#pragma unroll
    for (int k = 0; k < 32; k++) o_ = fmaf(s[OOUTW + k], fmaxf(net[k], 0.f), o_);

    out[(size_t)b * T_ + t] = o_;
}

extern "C" void kernel_launch(void* const* d_in, const int* in_sizes, int n_in,
                              void* d_out, int out_size) {
    const float* p        = (const float*)d_in[0];
    // d_in[1] = z (unused)
    const float* c        = (const float*)d_in[2];
    const float* C_mat    = (const float*)d_in[3];
    const float* fc_p_w   = (const float*)d_in[4];
    const float* fc_p_b   = (const float*)d_in[5];
    const float* blk0_w0  = (const float*)d_in[6];
    const float* blk0_b0  = (const float*)d_in[7];
    const float* blk0_w1  = (const float*)d_in[8];
    const float* blk0_b1  = (const float*)d_in[9];
    const float* blk0_ws  = (const float*)d_in[10];
    const float* blk_w0   = (const float*)d_in[11];
    const float* blk_b0   = (const float*)d_in[12];
    const float* blk_w1   = (const float*)d_in[13];
    const float* blk_b1   = (const float*)d_in[14];
    const float* fc_out_w = (const float*)d_in[15];
    const float* fc_out_b = (const float*)d_in[16];
    float* out = (float*)d_out;

    cudaFuncSetAttribute(decoder_kernel,
                         cudaFuncAttributeMaxDynamicSharedMemorySize, SMEM_BYTES);

    fold_kernel<<<1, 32>>>(blk0_ws, fc_p_w, fc_p_b);

    dim3 grid((T_ + 255) / 256, B_);
    decoder_kernel<<<grid, 256, SMEM_BYTES>>>(
        p, c, C_mat, blk0_w0, blk0_b0, blk0_w1, blk0_b1,
        blk_w0, blk_b0, blk_w1, blk_b1, fc_out_w, fc_out_b,
        fc_p_w, fc_p_b, out);
}

// round 2
// speedup vs baseline: 1.0018x; 1.0018x over previous
#include <cuda_runtime.h>
#include <math.h>

#define B_   8
#define T_   30000
#define L_   6
#define H_   128
#define W_   128
#define D_   32
#define HID_ 256

// Folded shortcut: blk0_ws @ fc_p_w  (32x3) and blk0_ws @ fc_p_b (32)
__device__ float g_foldW[32 * 3];
__device__ float g_foldB[32];

__global__ void fold_kernel(const float* __restrict__ ws,
                            const float* __restrict__ fw,
                            const float* __restrict__ fb) {
    int o = threadIdx.x;
    if (o >= 32) return;
    float a0 = 0.f, a1 = 0.f, a2 = 0.f, ab = 0.f;
    for (int k = 0; k < HID_; k++) {
        float w = ws[o * HID_ + k];
        a0 = fmaf(w, fw[k * 3 + 0], a0);
        a1 = fmaf(w, fw[k * 3 + 1], a1);
        a2 = fmaf(w, fw[k * 3 + 2], a2);
        ab = fmaf(w, fb[k], ab);
    }
    g_foldW[o * 3 + 0] = a0;
    g_foldW[o * 3 + 1] = a1;
    g_foldW[o * 3 + 2] = a2;
    g_foldB[o] = ab;
}

// ---- shared memory layout (float offsets) ----
#define OW0   0        /* blk0_w0      [32][256]  8192 */
#define OW1   8192     /* blk0_w1      [32][32]   1024 */
#define OBW0  9216     /* blk_w0    [4][32][32]   4096 */
#define OBW1  13312    /* blk_w1    [4][32][32]   4096 */
#define OFPW  17408    /* fc_p_w^T     [3][256]    768 */
#define OFPB  18176    /* fc_p_b          [256]    256 */
#define OB0   18432    /* blk0_b0          [32]     32 */
#define OB1   18464    /* blk0_b1          [32]     32 */
#define OBB0  18496    /* blk_b0        [4][32]    128 */
#define OBB1  18624    /* blk_b1        [4][32]    128 */
#define OFW   18752    /* foldW        [32][3]      96 */
#define OFB   18848    /* foldB           [32]      32 */
#define OOUTW 18880    /* fc_out_w        [32]      32 */
#define OA    18912    /* A          [6][2][3]      36 */
#define OOUTB 18948    /* fc_out_b                   1 */
#define SMEM_FLOATS 18949
#define SMEM_BYTES  (SMEM_FLOATS * 4)

__global__ __launch_bounds__(256, 2)
void decoder_kernel(const float* __restrict__ p,
                    const float* __restrict__ c,
                    const float* __restrict__ C_mat,
                    const float* __restrict__ blk0_w0,
                    const float* __restrict__ blk0_b0,
                    const float* __restrict__ blk0_w1,
                    const float* __restrict__ blk0_b1,
                    const float* __restrict__ blk_w0,
                    const float* __restrict__ blk_b0,
                    const float* __restrict__ blk_w1,
                    const float* __restrict__ blk_b1,
                    const float* __restrict__ fc_out_w,
                    const float* __restrict__ fc_out_b,
                    const float* __restrict__ fc_p_w,
                    const float* __restrict__ fc_p_b,
                    float* __restrict__ out) {
    extern __shared__ float s[];
    const int tid = threadIdx.x;
    const int b   = blockIdx.y;

    // ---- cooperative weight staging ----
    for (int i = tid; i < 8192; i += 256) s[OW0 + i]  = blk0_w0[i];
    for (int i = tid; i < 1024; i += 256) s[OW1 + i]  = blk0_w1[i];
    for (int i = tid; i < 4096; i += 256) s[OBW0 + i] = blk_w0[i];
    for (int i = tid; i < 4096; i += 256) s[OBW1 + i] = blk_w1[i];
    for (int i = tid; i < 768; i += 256) {                 // transpose fc_p_w -> [3][256]
        int j = i / 256, k = i % 256;
        s[OFPW + i] = fc_p_w[k * 3 + j];
    }
    for (int i = tid; i < 256; i += 256) s[OFPB + i] = fc_p_b[i];
    if (tid < 32)  s[OB0 + tid]  = blk0_b0[tid];
    if (tid < 32)  s[OB1 + tid]  = blk0_b1[tid];
    if (tid < 128) s[OBB0 + tid] = blk_b0[tid];
    if (tid < 128) s[OBB1 + tid] = blk_b1[tid];
    if (tid < 96)  s[OFW + tid]  = g_foldW[tid];
    if (tid < 32)  s[OFB + tid]  = g_foldB[tid];
    if (tid < 32)  s[OOUTW + tid] = fc_out_w[tid];
    if (tid == 0)  s[OOUTB] = fc_out_b[0];
    if (tid < 36) {
        int l = tid / 6, r = tid % 6, i2 = r / 3, j = r % 3;
        float denom = C_mat[((b * L_ + l) * 4 + 3) * 3 + 0] + 0.05f;
        s[OA + tid] = C_mat[((b * L_ + l) * 4 + i2) * 3 + j] * (63.5f / (0.55f * denom));
    }
    __syncthreads();

    const int t = blockIdx.x * 256 + tid;
    if (t >= T_) return;

    const float* pp = p + ((size_t)b * T_ + t) * 3;
    const float p0 = pp[0], p1 = pp[1], p2 = pp[2];

    // ---- bilinear gather + view-sum -> feat[32] ----
    float feat[32];
#pragma unroll
    for (int d = 0; d < 32; d++) feat[d] = 0.f;

#pragma unroll 1
    for (int l = 0; l < L_; l++) {
        const float* Al = s + OA + l * 6;
        float x = fmaf(Al[0], p0, fmaf(Al[1], p1, fmaf(Al[2], p2, 63.5f)));
        float y = fmaf(Al[3], p0, fmaf(Al[4], p1, fmaf(Al[5], p2, 63.5f)));
        float x0f = floorf(x), x1f = ceilf(x);
        float y0f = floorf(y), y1f = ceilf(y);
        float dx = x1f - x, dy = y1f - y;
        int ix0 = min(max((int)x0f, 0), H_ - 1);
        int ix1 = min(max((int)x1f, 0), H_ - 1);
        int iy0 = min(max((int)y0f, 0), W_ - 1);
        int iy1 = min(max((int)y1f, 0), W_ - 1);
        const float* cb = c + ((size_t)(b * L_ + l)) * (H_ * W_ * D_);
        const float4* f11 = (const float4*)(cb + (ix0 * W_ + iy0) * D_);
        const float4* f12 = (const float4*)(cb + (ix1 * W_ + iy0) * D_);
        const float4* f21 = (const float4*)(cb + (ix0 * W_ + iy1) * D_);
        const float4* f22 = (const float4*)(cb + (ix1 * W_ + iy1) * D_);
        float w11 = dx * dy;
        float w12 = (1.f - dx) * dy;
        float w21 = dx * (1.f - dy);
        float w22 = (1.f - dx) * (1.f - dy);
#pragma unroll
        for (int d = 0; d < 8; d++) {
            float4 a = f11[d], bb = f12[d], cc = f21[d], dd = f22[d];
            feat[4 * d + 0] = fmaf(w11, a.x, fmaf(w12, bb.x, fmaf(w21, cc.x, fmaf(w22, dd.x, feat[4 * d + 0]))));
            feat[4 * d + 1] = fmaf(w11, a.y, fmaf(w12, bb.y, fmaf(w21, cc.y, fmaf(w22, dd.y, feat[4 * d + 1]))));
            feat[4 * d + 2] = fmaf(w11, a.z, fmaf(w12, bb.z, fmaf(w21, cc.z, fmaf(w22, dd.z, feat[4 * d + 2]))));
            feat[4 * d + 3] = fmaf(w11, a.w, fmaf(w12, bb.w, fmaf(w21, cc.w, fmaf(w22, dd.w, feat[4 * d + 3]))));
        }
    }

    // ---- 3 -> 256 (relu) -> 32 fused, accumulating h ----
    float acc[32];
#pragma unroll
    for (int o = 0; o < 32; o++) acc[o] = s[OB0 + o];

#pragma unroll 1
    for (int k = 0; k < HID_; k += 4) {
        float4 wa = *(const float4*)&s[OFPW + k];
        float4 wb = *(const float4*)&s[OFPW + 256 + k];
        float4 wc = *(const float4*)&s[OFPW + 512 + k];
        float4 bv = *(const float4*)&s[OFPB + k];
        float r0 = fmaxf(fmaf(wa.x, p0, fmaf(wb.x, p1, fmaf(wc.x, p2, bv.x))), 0.f);
        float r1 = fmaxf(fmaf(wa.y, p0, fmaf(wb.y, p1, fmaf(wc.y, p2, bv.y))), 0.f);
        float r2 = fmaxf(fmaf(wa.z, p0, fmaf(wb.z, p1, fmaf(wc.z, p2, bv.z))), 0.f);
        float r3 = fmaxf(fmaf(wa.w, p0, fmaf(wb.w, p1, fmaf(wc.w, p2, bv.w))), 0.f);
#pragma unroll
        for (int o = 0; o < 32; o++) {
            float4 w = *(const float4*)&s[OW0 + o * HID_ + k];
            acc[o] = fmaf(w.x, r0, fmaf(w.y, r1, fmaf(w.z, r2, fmaf(w.w, r3, acc[o]))));
        }
    }

    // relu(h) in place
#pragma unroll
    for (int o = 0; o < 32; o++) acc[o] = fmaxf(acc[o], 0.f);

    // net = foldW*p + foldB + blk0_b1 + feat, then += blk0_w1 @ relu(h)
    float net[32];
#pragma unroll
    for (int o = 0; o < 32; o++) {
        net[o] = fmaf(s[OFW + o * 3 + 0], p0,
                 fmaf(s[OFW + o * 3 + 1], p1,
                 fmaf(s[OFW + o * 3 + 2], p2,
                      s[OFB + o] + s[OB1 + o] + feat[o])));
    }
#pragma unroll
    for (int k = 0; k < 32; k += 4) {
        float r0 = acc[k], r1 = acc[k + 1], r2 = acc[k + 2], r3 = acc[k + 3];
#pragma unroll
        for (int o = 0; o < 32; o++) {
            float4 w = *(const float4*)&s[OW1 + o * 32 + k];
            net[o] = fmaf(w.x, r0, fmaf(w.y, r1, fmaf(w.z, r2, fmaf(w.w, r3, net[o]))));
        }
    }

    // ---- 4 residual blocks (32 -> 32 -> 32) ----
#pragma unroll 1
    for (int i = 0; i < 4; i++) {
        const float* w0p = s + OBW0 + i * 1024;
        const float* w1p = s + OBW1 + i * 1024;
        const float* b0p = s + OBB0 + i * 32;
        const float* b1p = s + OBB1 + i * 32;
        float h[32];
#pragma unroll
        for (int o = 0; o < 32; o++) h[o] = b0p[o];
#pragma unroll
        for (int k = 0; k < 32; k += 4) {
            float r0 = fmaxf(net[k], 0.f);
            float r1 = fmaxf(net[k + 1], 0.f);
            float r2 = fmaxf(net[k + 2], 0.f);
            float r3 = fmaxf(net[k + 3], 0.f);
#pragma unroll
            for (int o = 0; o < 32; o++) {
                float4 w = *(const float4*)&w0p[o * 32 + k];
                h[o] = fmaf(w.x, r0, fmaf(w.y, r1, fmaf(w.z, r2, fmaf(w.w, r3, h[o]))));
            }
        }
#pragma unroll
        for (int o = 0; o < 32; o++) net[o] += b1p[o] + feat[o];
#pragma unroll
        for (int k = 0; k < 32; k += 4) {
            float r0 = fmaxf(h[k], 0.f);
            float r1 = fmaxf(h[k + 1], 0.f);
            float r2 = fmaxf(h[k + 2], 0.f);
            float r3 = fmaxf(h[k + 3], 0.f);
#pragma unroll
            for (int o = 0; o < 32; o++) {
                float4 w = *(const float4*)&w1p[o * 32 + k];
                net[o] = fmaf(w.x, r0, fmaf(w.y, r1, fmaf(w.z, r2, fmaf(w.w, r3, net[o]))));
            }
        }
    }

    // ---- output head ----
    float o_ = s[OOUTB];
#pragma unroll
    for (int k = 0; k < 32; k++) o_ = fmaf(s[OOUTW + k], fmaxf(net[k], 0.f), o_);

    out[(size_t)b * T_ + t] = o_;
}

extern "C" void kernel_launch(void* const* d_in, const int* in_sizes, int n_in,
                              void* d_out, int out_size) {
    const float* p        = (const float*)d_in[0];
    // d_in[1] = z (unused)
    const float* c        = (const float*)d_in[2];
    const float* C_mat    = (const float*)d_in[3];
    const float* fc_p_w   = (const float*)d_in[4];
    const float* fc_p_b   = (const float*)d_in[5];
    const float* blk0_w0  = (const float*)d_in[6];
    const float* blk0_b0  = (const float*)d_in[7];
    const float* blk0_w1  = (const float*)d_in[8];
    const float* blk0_b1  = (const float*)d_in[9];
    const float* blk0_ws  = (const float*)d_in[10];
    const float* blk_w0   = (const float*)d_in[11];
    const float* blk_b0   = (const float*)d_in[12];
    const float* blk_w1   = (const float*)d_in[13];
    const float* blk_b1   = (const float*)d_in[14];
    const float* fc_out_w = (const float*)d_in[15];
    const float* fc_out_b = (const float*)d_in[16];
    float* out = (float*)d_out;

    cudaFuncSetAttribute(decoder_kernel,
                         cudaFuncAttributeMaxDynamicSharedMemorySize, SMEM_BYTES);

    fold_kernel<<<1, 32>>>(blk0_ws, fc_p_w, fc_p_b);

    dim3 grid((T_ + 255) / 256, B_);
    decoder_kernel<<<grid, 256, SMEM_BYTES>>>(
        p, c, C_mat, blk0_w0, blk0_b0, blk0_w1, blk0_b1,
        blk_w0, blk_b0, blk_w1, blk_b1, fc_out_w, fc_out_b,
        fc_p_w, fc_p_b, out);
}